// round 6
// baseline (speedup 1.0000x reference)
#include <cuda_runtime.h>
#include <math.h>
#include <stdint.h>

// ---------------------------------------------------------------------------
// Problem constants
// ---------------------------------------------------------------------------
#define NTOK   81
#define DM     512
#define NH     8
#define EH     64
#define DFF    1024
#define NL     3
#define RT     (2048 * 81)           // 165888 tokens
#define RTILES (RT / 128)            // 1296

// ---------------------------------------------------------------------------
// Scratch (device globals: no cudaMalloc allowed)
// ---------------------------------------------------------------------------
__device__ float g_h  [RT * DM];
__device__ float g_q  [RT * DM];
__device__ float g_k  [RT * DM];
__device__ float g_v  [RT * DM];
__device__ float g_att[RT * DM];
__device__ float g_y  [RT * DM];
__device__ float g_t  [RT * DFF];
__device__ float g_psum[512 * 512];
__device__ float g_psq [512 * 512];
__device__ float g_bnscale[2 * 512];
__device__ float g_bnshift[2 * 512];

// ---------------------------------------------------------------------------
// tf32 / ldmatrix helpers
// ---------------------------------------------------------------------------
__device__ __forceinline__ float tf32r(float x) {
    float y;
    asm("cvt.rna.tf32.f32 %0, %1;" : "=f"(y) : "f"(x));
    return y;
}

__device__ __forceinline__ void mma_tf32(float* c, const uint32_t* a, const uint32_t* b) {
    asm volatile(
        "mma.sync.aligned.m16n8k8.row.col.f32.tf32.tf32.f32 "
        "{%0,%1,%2,%3}, {%4,%5,%6,%7}, {%8,%9}, {%0,%1,%2,%3};"
        : "+f"(c[0]), "+f"(c[1]), "+f"(c[2]), "+f"(c[3])
        : "r"(a[0]), "r"(a[1]), "r"(a[2]), "r"(a[3]), "r"(b[0]), "r"(b[1]));
}

__device__ __forceinline__ void ldsm_x4(uint32_t* r, uint32_t addr) {
    asm volatile("ldmatrix.sync.aligned.m8n8.x4.shared.b16 {%0,%1,%2,%3}, [%4];"
        : "=r"(r[0]), "=r"(r[1]), "=r"(r[2]), "=r"(r[3]) : "r"(addr));
}

// ---------------------------------------------------------------------------
// TF32 GEMM: C[r,o] = sum_k A[r,k]*W[o,k] (+bias)
// CTA tile 128(rows) x 256(cols), BK=16, 8 warps (2 row x 4 col),
// warp tile 64x64 -> acc[4][8][4]. Double-buffered dynamic smem.
// EPI: 0=bias, 1=bias+gelu, 2=bias+residual
// AFF: 0=none, 1=affine on A (per-K channel), 2=affine on residual (per-col)
// ---------------------------------------------------------------------------
#define APAD 20
#define A_BUF_F (128 * APAD)          // floats per A buffer
#define B_BUF_F (256 * APAD)
#define GEMM_SMEM ((2 * A_BUF_F + 2 * B_BUF_F) * 4)   // 61440 B

template <int EPI, int AFF>
__global__ __launch_bounds__(256)
void mma_gemm(const float* __restrict__ A, const float* __restrict__ W,
              const float* __restrict__ bias, const float* __restrict__ res,
              const float* __restrict__ scl, const float* __restrict__ shf,
              float* __restrict__ C, int K)
{
    extern __shared__ float smf[];
    float* Asf = smf;                  // [2][128][APAD]
    float* Bsf = smf + 2 * A_BUF_F;    // [2][256][APAD]

    int tid  = threadIdx.x;
    int wid  = tid >> 5, lane = tid & 31;
    int wm   = (wid >> 2) * 64;        // warp row offset (0/64)
    int wn   = (wid & 3) * 64;         // warp col offset (0..192)
    int row0 = blockIdx.y * 128, col0 = blockIdx.x * 256;
    int Dout = gridDim.x * 256;
    int qg   = lane >> 2, qt = lane & 3;
    int lg   = lane >> 3, lr = lane & 7;

    uint32_t asu = (uint32_t)__cvta_generic_to_shared(Asf);
    uint32_t bsu = (uint32_t)__cvta_generic_to_shared(Bsf);
    uint32_t baseA[4], baseB[4];
    #pragma unroll
    for (int mt = 0; mt < 4; mt++)
        baseA[mt] = asu + (((wm + mt * 16 + (lg & 1) * 8 + lr) * APAD) + (lg >> 1) * 4) * 4;
    #pragma unroll
    for (int p = 0; p < 4; p++)
        baseB[p]  = bsu + (((wn + (2 * p + (lg >> 1)) * 8 + lr) * APAD) + (lg & 1) * 4) * 4;
    const uint32_t BUFA = A_BUF_F * 4, BUFB = B_BUF_F * 4;

    // gmem mapping: A 2 float4/thread (128x16), B 4 float4/thread (256x16)
    int ra[2], ka[2], rb[4], kb4[4];
    #pragma unroll
    for (int i = 0; i < 2; i++) {
        int lin = tid + 256 * i;
        ra[i] = lin >> 2; ka[i] = lin & 3;
    }
    #pragma unroll
    for (int i = 0; i < 4; i++) {
        int lin = tid + 256 * i;
        rb[i] = lin >> 2; kb4[i] = lin & 3;
    }

    float4 pa[2], pb[4];
    #pragma unroll
    for (int i = 0; i < 2; i++)
        pa[i] = *(const float4*)(A + (size_t)(row0 + ra[i]) * K + ka[i] * 4);
    #pragma unroll
    for (int i = 0; i < 4; i++)
        pb[i] = *(const float4*)(W + (size_t)(col0 + rb[i]) * K + kb4[i] * 4);

    #pragma unroll
    for (int i = 0; i < 2; i++) {
        float4 va = pa[i];
        if (AFF == 1) {
            float4 s4 = *(const float4*)(scl + ka[i] * 4);
            float4 h4 = *(const float4*)(shf + ka[i] * 4);
            va.x = s4.x * va.x + h4.x; va.y = s4.y * va.y + h4.y;
            va.z = s4.z * va.z + h4.z; va.w = s4.w * va.w + h4.w;
        }
        va.x = tf32r(va.x); va.y = tf32r(va.y); va.z = tf32r(va.z); va.w = tf32r(va.w);
        *(float4*)&Asf[ra[i] * APAD + ka[i] * 4] = va;
    }
    #pragma unroll
    for (int i = 0; i < 4; i++) {
        float4 vb = pb[i];
        vb.x = tf32r(vb.x); vb.y = tf32r(vb.y); vb.z = tf32r(vb.z); vb.w = tf32r(vb.w);
        *(float4*)&Bsf[rb[i] * APAD + kb4[i] * 4] = vb;
    }
    __syncthreads();

    float acc[4][8][4];
    #pragma unroll
    for (int mt = 0; mt < 4; mt++)
        #pragma unroll
        for (int nt = 0; nt < 8; nt++)
            #pragma unroll
            for (int j = 0; j < 4; j++) acc[mt][nt][j] = 0.f;

    int NKB = K / 16;
    for (int kb = 0; kb < NKB; kb++) {
        int cur = kb & 1, nxt = cur ^ 1;
        if (kb + 1 < NKB) {
            int kOff = (kb + 1) * 16;
            #pragma unroll
            for (int i = 0; i < 2; i++)
                pa[i] = *(const float4*)(A + (size_t)(row0 + ra[i]) * K + kOff + ka[i] * 4);
            #pragma unroll
            for (int i = 0; i < 4; i++)
                pb[i] = *(const float4*)(W + (size_t)(col0 + rb[i]) * K + kOff + kb4[i] * 4);
        }

        uint32_t aOff = cur * BUFA, bOff = cur * BUFB;
        #pragma unroll
        for (int ks = 0; ks < 2; ks++) {
            uint32_t kB = ks * 32;
            uint32_t af[4][4], bf[8][2];
            #pragma unroll
            for (int mt = 0; mt < 4; mt++)
                ldsm_x4(af[mt], baseA[mt] + aOff + kB);
            #pragma unroll
            for (int p = 0; p < 4; p++) {
                uint32_t t[4];
                ldsm_x4(t, baseB[p] + bOff + kB);
                bf[2 * p][0] = t[0]; bf[2 * p][1] = t[1];
                bf[2 * p + 1][0] = t[2]; bf[2 * p + 1][1] = t[3];
            }
            #pragma unroll
            for (int mt = 0; mt < 4; mt++)
                #pragma unroll
                for (int nt = 0; nt < 8; nt++)
                    mma_tf32(acc[mt][nt], af[mt], bf[nt]);
        }

        if (kb + 1 < NKB) {
            int kOff = (kb + 1) * 16;
            #pragma unroll
            for (int i = 0; i < 2; i++) {
                float4 va = pa[i];
                if (AFF == 1) {
                    float4 s4 = *(const float4*)(scl + kOff + ka[i] * 4);
                    float4 h4 = *(const float4*)(shf + kOff + ka[i] * 4);
                    va.x = s4.x * va.x + h4.x; va.y = s4.y * va.y + h4.y;
                    va.z = s4.z * va.z + h4.z; va.w = s4.w * va.w + h4.w;
                }
                va.x = tf32r(va.x); va.y = tf32r(va.y); va.z = tf32r(va.z); va.w = tf32r(va.w);
                *(float4*)&Asf[nxt * A_BUF_F + ra[i] * APAD + ka[i] * 4] = va;
            }
            #pragma unroll
            for (int i = 0; i < 4; i++) {
                float4 vb = pb[i];
                vb.x = tf32r(vb.x); vb.y = tf32r(vb.y); vb.z = tf32r(vb.z); vb.w = tf32r(vb.w);
                *(float4*)&Bsf[nxt * B_BUF_F + rb[i] * APAD + kb4[i] * 4] = vb;
            }
        }
        __syncthreads();
    }

    // epilogue
    #pragma unroll
    for (int mt = 0; mt < 4; mt++) {
        #pragma unroll
        for (int nt = 0; nt < 8; nt++) {
            int c  = col0 + wn + nt * 8 + 2 * qt;
            int r0 = row0 + wm + mt * 16 + qg;
            float b0 = bias[c], b1 = bias[c + 1];
            float s0 = 1.f, s1 = 1.f, h0 = 0.f, h1 = 0.f;
            if (AFF == 2) {
                s0 = scl[c]; s1 = scl[c + 1];
                h0 = shf[c]; h1 = shf[c + 1];
            }
            #pragma unroll
            for (int half = 0; half < 2; half++) {
                int r = r0 + half * 8;
                float vx = acc[mt][nt][half * 2 + 0] + b0;
                float vy = acc[mt][nt][half * 2 + 1] + b1;
                if (EPI == 1) {
                    vx = 0.5f * vx * (1.0f + erff(vx * 0.70710678118654752f));
                    vy = 0.5f * vy * (1.0f + erff(vy * 0.70710678118654752f));
                }
                size_t off = (size_t)r * Dout + c;
                if (EPI == 2) {
                    float2 rv = *(const float2*)(res + off);
                    if (AFF == 2) { vx += s0 * rv.x + h0; vy += s1 * rv.y + h1; }
                    else          { vx += rv.x;           vy += rv.y; }
                }
                *(float2*)(C + off) = make_float2(vx, vy);
            }
        }
    }
}

// ---------------------------------------------------------------------------
// Token embedding: circular Conv1d(P->D,k=3) + sinusoidal PE
// ---------------------------------------------------------------------------
#define EMB_SMEM_FLOATS (512 * 49 + 336)
__global__ void embed_kernel(const float* __restrict__ x_enc,
                             const float* __restrict__ tok_w,
                             float* __restrict__ h)
{
    extern __shared__ float sm[];
    float* w_sm = sm;
    float* x_sm = sm + 512 * 49;
    int bm = blockIdx.x;
    int b = bm >> 6, m = bm & 63;
    int tid = threadIdx.x;

    for (int i = tid; i < 512 * 48; i += 256) {
        int d = i / 48, u = i - d * 48;
        w_sm[d * 49 + u] = tok_w[i];
    }
    for (int l = tid; l < 336; l += 256)
        x_sm[l] = x_enc[(b * 336 + l) * 64 + m];
    __syncthreads();

    const float CLOG = -9.210340371976184f / 256.0f;
    int d0 = tid, d1 = tid + 256;
    float fr0 = expf((float)(d0 >> 1) * CLOG);
    float fr1 = expf((float)(d1 >> 1) * CLOG);

    for (int n = 0; n < NTOK; n++) {
        float a0 = 0.f, a1 = 0.f;
        #pragma unroll
        for (int t = 0; t < 3; t++) {
            int pp = n - 1 + t;
            pp = (pp < 0) ? (NTOK - 1) : (pp >= NTOK ? 0 : pp);
            const float* xp = x_sm + pp * 4;
            #pragma unroll
            for (int p = 0; p < 16; p++) {
                float xv = xp[p];
                a0 += xv * w_sm[d0 * 49 + p * 3 + t];
                a1 += xv * w_sm[d1 * 49 + p * 3 + t];
            }
        }
        float ang0 = (float)n * fr0, ang1 = (float)n * fr1;
        float pe0 = (d0 & 1) ? cosf(ang0) : sinf(ang0);
        float pe1 = (d1 & 1) ? cosf(ang1) : sinf(ang1);
        size_t base = ((size_t)bm * NTOK + n) * DM;
        h[base + d0] = a0 + pe0;
        h[base + d1] = a1 + pe1;
    }
}

// ---------------------------------------------------------------------------
// Fused attention per (bm, head), register-microtiled
// ---------------------------------------------------------------------------
#define QPAD 17
#define SPAD 84
#define ATTN_SMEM_FLOATS (3 * 81 * 68 + 81 * SPAD)
__global__ void attn_kernel(const float* __restrict__ q,
                            const float* __restrict__ k,
                            const float* __restrict__ v,
                            float* __restrict__ o)
{
    extern __shared__ float sm[];
    float4* qs4 = (float4*)sm;
    float4* ks4 = qs4 + 81 * QPAD;
    float4* vs4 = ks4 + 81 * QPAD;
    float*  ss  = sm + 3 * 81 * 68;
    int bmh = blockIdx.x;
    int bm = bmh >> 3, hh = bmh & 7;
    int tid = threadIdx.x;
    size_t base = (size_t)bm * NTOK * DM + hh * EH;

    const float4* gq = (const float4*)(q + base);
    const float4* gk = (const float4*)(k + base);
    const float4* gv = (const float4*)(v + base);
    for (int i = tid; i < NTOK * 16; i += 256) {
        int n = i >> 4, e4 = i & 15;
        int gi = n * 128 + e4;
        qs4[n * QPAD + e4] = gq[gi];
        ks4[n * QPAD + e4] = gk[gi];
        vs4[n * QPAD + e4] = gv[gi];
    }
    __syncthreads();

    for (int i = tid; i < 729; i += 256) {
        int l0 = (i / 27) * 3, s0 = (i % 27) * 3;
        float acc[3][3] = {};
        #pragma unroll 4
        for (int e4 = 0; e4 < 16; e4++) {
            float4 qv[3], kv[3];
            #pragma unroll
            for (int j = 0; j < 3; j++) {
                qv[j] = qs4[(l0 + j) * QPAD + e4];
                kv[j] = ks4[(s0 + j) * QPAD + e4];
            }
            #pragma unroll
            for (int a = 0; a < 3; a++)
                #pragma unroll
                for (int b2 = 0; b2 < 3; b2++)
                    acc[a][b2] += qv[a].x * kv[b2].x + qv[a].y * kv[b2].y
                                + qv[a].z * kv[b2].z + qv[a].w * kv[b2].w;
        }
        #pragma unroll
        for (int a = 0; a < 3; a++)
            #pragma unroll
            for (int b2 = 0; b2 < 3; b2++)
                ss[(l0 + a) * SPAD + s0 + b2] = acc[a][b2] * 0.125f;
    }
    __syncthreads();

    if (tid < NTOK) {
        float* row = ss + tid * SPAD;
        float mx = -1e30f;
        for (int s2 = 0; s2 < NTOK; s2++) mx = fmaxf(mx, row[s2]);
        float sum = 0.f;
        for (int s2 = 0; s2 < NTOK; s2++) {
            float t = expf(row[s2] - mx);
            row[s2] = t; sum += t;
        }
        float inv = 1.0f / sum;
        for (int s2 = 0; s2 < NTOK; s2++) row[s2] *= inv;
    }
    __syncthreads();

    float4* go = (float4*)(o + base);
    for (int i = tid; i < 432; i += 256) {
        int l0 = (i / 16) * 3, e4 = i % 16;
        float4 acc[3] = {};
        for (int s2 = 0; s2 < NTOK; s2++) {
            float4 vv = vs4[s2 * QPAD + e4];
            #pragma unroll
            for (int j = 0; j < 3; j++) {
                float a = ss[(l0 + j) * SPAD + s2];
                acc[j].x += a * vv.x; acc[j].y += a * vv.y;
                acc[j].z += a * vv.z; acc[j].w += a * vv.w;
            }
        }
        #pragma unroll
        for (int j = 0; j < 3; j++)
            go[(l0 + j) * 128 + e4] = acc[j];
    }
}

// ---------------------------------------------------------------------------
// BatchNorm stats
// ---------------------------------------------------------------------------
__global__ void bn_reduce1_kernel(const float* __restrict__ y)
{
    int c = threadIdx.x;
    const float* p = y + (size_t)blockIdx.x * 324 * DM + c;
    float s = 0.f, q = 0.f;
    #pragma unroll 4
    for (int i = 0; i < 324; i++) {
        float vv = p[(size_t)i * DM];
        s += vv; q += vv * vv;
    }
    g_psum[blockIdx.x * 512 + c] = s;
    g_psq [blockIdx.x * 512 + c] = q;
}

__global__ void bn_reduce2_kernel(const float* __restrict__ gamma,
                                  const float* __restrict__ beta,
                                  float* __restrict__ scl,
                                  float* __restrict__ shf)
{
    int c = blockIdx.x * 256 + threadIdx.x;
    float s = 0.f, q = 0.f;
    for (int j = 0; j < 512; j++) {
        s += g_psum[j * 512 + c];
        q += g_psq [j * 512 + c];
    }
    const float invn = 1.0f / (float)RT;
    float mu  = s * invn;
    float var = q * invn - mu * mu;
    float rinv = rsqrtf(var + 1e-5f);
    float sc = rinv * gamma[c];
    scl[c] = sc;
    shf[c] = beta[c] - mu * sc;
}

__global__ void bn_norm_kernel(const float* __restrict__ y,
                               const float* __restrict__ scl,
                               const float* __restrict__ shf,
                               float* __restrict__ out)
{
    const int total = RT * DM / 4;
    for (int i = blockIdx.x * blockDim.x + threadIdx.x; i < total;
         i += gridDim.x * blockDim.x) {
        float4 vv = ((const float4*)y)[i];
        int c = (i & 127) * 4;
        float4 oo;
        oo.x = vv.x * scl[c + 0] + shf[c + 0];
        oo.y = vv.y * scl[c + 1] + shf[c + 1];
        oo.z = vv.z * scl[c + 2] + shf[c + 2];
        oo.w = vv.w * scl[c + 3] + shf[c + 3];
        ((float4*)out)[i] = oo;
    }
}

// ---------------------------------------------------------------------------
// Orchestration
// ---------------------------------------------------------------------------
extern "C" void kernel_launch(void* const* d_in, const int* in_sizes, int n_in,
                              void* d_out, int out_size)
{
    const float* x_enc = (const float*)d_in[0];
    const float* tok_w = (const float*)d_in[1];
    const float* wq  = (const float*)d_in[2];
    const float* bq  = (const float*)d_in[3];
    const float* wk  = (const float*)d_in[4];
    const float* bk  = (const float*)d_in[5];
    const float* wv  = (const float*)d_in[6];
    const float* bv  = (const float*)d_in[7];
    const float* wo  = (const float*)d_in[8];
    const float* bo  = (const float*)d_in[9];
    const float* c1w = (const float*)d_in[10];
    const float* c1b = (const float*)d_in[11];
    const float* c2w = (const float*)d_in[12];
    const float* c2b = (const float*)d_in[13];
    const float* g1  = (const float*)d_in[14];
    const float* be1 = (const float*)d_in[15];
    const float* g2  = (const float*)d_in[16];
    const float* be2 = (const float*)d_in[17];
    float* out = (float*)d_out;

    float *p_h, *p_q, *p_k, *p_v, *p_att, *p_y, *p_t, *p_scl, *p_shf;
    cudaGetSymbolAddress((void**)&p_h,   g_h);
    cudaGetSymbolAddress((void**)&p_q,   g_q);
    cudaGetSymbolAddress((void**)&p_k,   g_k);
    cudaGetSymbolAddress((void**)&p_v,   g_v);
    cudaGetSymbolAddress((void**)&p_att, g_att);
    cudaGetSymbolAddress((void**)&p_y,   g_y);
    cudaGetSymbolAddress((void**)&p_t,   g_t);
    cudaGetSymbolAddress((void**)&p_scl, g_bnscale);
    cudaGetSymbolAddress((void**)&p_shf, g_bnshift);
    float* scl0 = p_scl;       float* shf0 = p_shf;
    float* scl1 = p_scl + 512; float* shf1 = p_shf + 512;

    const int EMB_SMEM  = EMB_SMEM_FLOATS  * 4;
    const int ATTN_SMEM = ATTN_SMEM_FLOATS * 4;
    cudaFuncSetAttribute(embed_kernel,
        cudaFuncAttributeMaxDynamicSharedMemorySize, EMB_SMEM);
    cudaFuncSetAttribute(attn_kernel,
        cudaFuncAttributeMaxDynamicSharedMemorySize, ATTN_SMEM);
    cudaFuncSetAttribute(mma_gemm<0, 0>,
        cudaFuncAttributeMaxDynamicSharedMemorySize, GEMM_SMEM);
    cudaFuncSetAttribute(mma_gemm<0, 1>,
        cudaFuncAttributeMaxDynamicSharedMemorySize, GEMM_SMEM);
    cudaFuncSetAttribute(mma_gemm<2, 0>,
        cudaFuncAttributeMaxDynamicSharedMemorySize, GEMM_SMEM);
    cudaFuncSetAttribute(mma_gemm<2, 2>,
        cudaFuncAttributeMaxDynamicSharedMemorySize, GEMM_SMEM);
    cudaFuncSetAttribute(mma_gemm<1, 1>,
        cudaFuncAttributeMaxDynamicSharedMemorySize, GEMM_SMEM);

    embed_kernel<<<2048, 256, EMB_SMEM>>>(x_enc, tok_w, p_h);

    for (int l = 0; l < NL; l++) {
        const int WOFF = l * DM * DM;
        const int FOFF = l * DFF * DM;

        if (l == 0) {
            mma_gemm<0, 0><<<dim3(2, RTILES), 256, GEMM_SMEM>>>(p_h, wq + WOFF,
                bq + l * DM, nullptr, nullptr, nullptr, p_q, DM);
            mma_gemm<0, 0><<<dim3(2, RTILES), 256, GEMM_SMEM>>>(p_h, wk + WOFF,
                bk + l * DM, nullptr, nullptr, nullptr, p_k, DM);
            mma_gemm<0, 0><<<dim3(2, RTILES), 256, GEMM_SMEM>>>(p_h, wv + WOFF,
                bv + l * DM, nullptr, nullptr, nullptr, p_v, DM);
        } else {
            mma_gemm<0, 1><<<dim3(2, RTILES), 256, GEMM_SMEM>>>(p_h, wq + WOFF,
                bq + l * DM, nullptr, scl1, shf1, p_q, DM);
            mma_gemm<0, 1><<<dim3(2, RTILES), 256, GEMM_SMEM>>>(p_h, wk + WOFF,
                bk + l * DM, nullptr, scl1, shf1, p_k, DM);
            mma_gemm<0, 1><<<dim3(2, RTILES), 256, GEMM_SMEM>>>(p_h, wv + WOFF,
                bv + l * DM, nullptr, scl1, shf1, p_v, DM);
        }

        attn_kernel<<<2048 * NH, 256, ATTN_SMEM>>>(p_q, p_k, p_v, p_att);

        if (l == 0)
            mma_gemm<2, 0><<<dim3(2, RTILES), 256, GEMM_SMEM>>>(p_att, wo + WOFF,
                bo + l * DM, p_h, nullptr, nullptr, p_y, DM);
        else
            mma_gemm<2, 2><<<dim3(2, RTILES), 256, GEMM_SMEM>>>(p_att, wo + WOFF,
                bo + l * DM, p_h, scl1, shf1, p_y, DM);

        bn_reduce1_kernel<<<512, 512>>>(p_y);
        bn_reduce2_kernel<<<2, 256>>>(g1 + l * DM, be1 + l * DM, scl0, shf0);

        mma_gemm<1, 1><<<dim3(4, RTILES), 256, GEMM_SMEM>>>(p_y, c1w + FOFF,
            c1b + l * DFF, nullptr, scl0, shf0, p_t, DM);
        mma_gemm<2, 2><<<dim3(2, RTILES), 256, GEMM_SMEM>>>(p_t, c2w + FOFF,
            c2b + l * DM, p_y, scl0, shf0, p_h, DFF);

        bn_reduce1_kernel<<<512, 512>>>(p_h);
        bn_reduce2_kernel<<<2, 256>>>(g2 + l * DM, be2 + l * DM, scl1, shf1);
    }

    bn_norm_kernel<<<4096, 256>>>(p_h, scl1, shf1, out);
}

// round 7
// speedup vs baseline: 1.2094x; 1.2094x over previous
#include <cuda_runtime.h>
#include <math.h>
#include <stdint.h>

// ---------------------------------------------------------------------------
// Problem constants
// ---------------------------------------------------------------------------
#define NTOK   81
#define DM     512
#define NH     8
#define EH     64
#define DFF    1024
#define NL     3
#define RT     (2048 * 81)           // 165888 tokens
#define RTILES (RT / 128)            // 1296

// ---------------------------------------------------------------------------
// Scratch (device globals: no cudaMalloc allowed)
// ---------------------------------------------------------------------------
__device__ float g_h  [RT * DM];
__device__ float g_q  [RT * DM];
__device__ float g_k  [RT * DM];
__device__ float g_v  [RT * DM];
__device__ float g_att[RT * DM];
__device__ float g_y  [RT * DM];
__device__ float g_t  [RT * DFF];
__device__ float g_psum[RTILES * 512];
__device__ float g_psq [RTILES * 512];
__device__ float g_bnscale[2 * 512];
__device__ float g_bnshift[2 * 512];

// ---------------------------------------------------------------------------
// PTX helpers
// ---------------------------------------------------------------------------
__device__ __forceinline__ uint32_t smem_u32(const void* p) {
    uint32_t a;
    asm("{ .reg .u64 t; cvta.to.shared.u64 t, %1; cvt.u32.u64 %0, t; }"
        : "=r"(a) : "l"(p));
    return a;
}

__device__ __forceinline__ void cp16(uint32_t dst, const void* src) {
    asm volatile("cp.async.cg.shared.global [%0], [%1], 16;"
                 :: "r"(dst), "l"(src) : "memory");
}
#define CP_COMMIT() asm volatile("cp.async.commit_group;" ::: "memory")

__device__ __forceinline__ void mma_tf32(float* c, const uint32_t* a, const uint32_t* b) {
    asm volatile(
        "mma.sync.aligned.m16n8k8.row.col.f32.tf32.tf32.f32 "
        "{%0,%1,%2,%3}, {%4,%5,%6,%7}, {%8,%9}, {%0,%1,%2,%3};"
        : "+f"(c[0]), "+f"(c[1]), "+f"(c[2]), "+f"(c[3])
        : "r"(a[0]), "r"(a[1]), "r"(a[2]), "r"(a[3]), "r"(b[0]), "r"(b[1]));
}

__device__ __forceinline__ void ldsm_x4(uint32_t* r, uint32_t addr) {
    asm volatile("ldmatrix.sync.aligned.m8n8.x4.shared.b16 {%0,%1,%2,%3}, [%4];"
        : "=r"(r[0]), "=r"(r[1]), "=r"(r[2]), "=r"(r[3]) : "r"(addr));
}

// ---------------------------------------------------------------------------
// TF32 GEMM: C[r,o] = sum_k A[r,k]*W[o,k] (+bias)
// CTA tile 128x128, BK=16, 8 warps (2x4), warp tile 64x32, 2 CTAs/SM.
// cp.async.cg 3-stage pipeline; tf32 via HW truncation of raw fp32.
// EPI: 0=bias, 1=bias+gelu, 2=bias+residual
// AFF: 0=none, 1=affine on A in-fragment (per-K), 2=affine on residual (per-col)
// STATS: 1 -> write per-CTA column sum/sumsq partials to g_psum/g_psq
// ---------------------------------------------------------------------------
#define APAD 20
#define STAGE_B 20480                    // (128*20 + 128*20) floats * 4
#define GEMM_SMEM (3 * STAGE_B)          // 61440 B

template <int EPI, int AFF, int STATS>
__global__ __launch_bounds__(256, 2)
void mma_gemm(const float* __restrict__ A, const float* __restrict__ W,
              const float* __restrict__ bias, const float* __restrict__ res,
              const float* __restrict__ scl, const float* __restrict__ shf,
              float* __restrict__ C, int K)
{
    extern __shared__ float smf[];
    uint32_t sA = smem_u32(smf);
    uint32_t sB = sA + 10240;

    int tid  = threadIdx.x;
    int wid  = tid >> 5, lane = tid & 31;
    int wm   = (wid >> 2) * 64;
    int wn   = (wid & 3) * 32;
    int row0 = blockIdx.y * 128, col0 = blockIdx.x * 128;
    int Dout = gridDim.x * 128;
    int qg   = lane >> 2, qt = lane & 3;
    int lg   = lane >> 3, lr = lane & 7;

    uint32_t baseA[4], baseB[2];
    #pragma unroll
    for (int mt = 0; mt < 4; mt++)
        baseA[mt] = sA + (((wm + mt * 16 + (lg & 1) * 8 + lr) * APAD) + (lg >> 1) * 4) * 4;
    #pragma unroll
    for (int p = 0; p < 2; p++)
        baseB[p]  = sB + (((wn + (2 * p + (lg >> 1)) * 8 + lr) * APAD) + (lg & 1) * 4) * 4;

    // copy slots: 128 rows x 4 float4-slots = 512 slots / 256 threads = 2 each
    int ra[2], ka[2];
    #pragma unroll
    for (int i = 0; i < 2; i++) {
        int lin = tid + 256 * i;
        ra[i] = lin >> 2; ka[i] = lin & 3;
    }

    auto issue = [&](int st, int kb2) {
        #pragma unroll
        for (int i = 0; i < 2; i++) {
            cp16(sA + st * STAGE_B + (ra[i] * APAD + ka[i] * 4) * 4,
                 A + (size_t)(row0 + ra[i]) * K + kb2 * 16 + ka[i] * 4);
            cp16(sB + st * STAGE_B + (ra[i] * APAD + ka[i] * 4) * 4,
                 W + (size_t)(col0 + ra[i]) * K + kb2 * 16 + ka[i] * 4);
        }
        CP_COMMIT();
    };

    int NKB = K / 16;
    issue(0, 0);
    issue(1, 1);

    float acc[4][4][4];
    #pragma unroll
    for (int mt = 0; mt < 4; mt++)
        #pragma unroll
        for (int nt = 0; nt < 4; nt++)
            #pragma unroll
            for (int j = 0; j < 4; j++) acc[mt][nt][j] = 0.f;

    int st = 0, nst = 2;
    for (int kb = 0; kb < NKB; kb++) {
        if (kb + 1 < NKB)
            asm volatile("cp.async.wait_group 1;" ::: "memory");
        else
            asm volatile("cp.async.wait_group 0;" ::: "memory");
        __syncthreads();
        if (kb + 2 < NKB) {
            issue(nst, kb + 2);
            if (++nst == 3) nst = 0;
        }

        uint32_t stOff = st * STAGE_B;
        #pragma unroll
        for (int ks = 0; ks < 2; ks++) {
            uint32_t kB = stOff + ks * 32;
            uint32_t af[4][4], bf[4][2];
            #pragma unroll
            for (int mt = 0; mt < 4; mt++)
                ldsm_x4(af[mt], baseA[mt] + kB);
            #pragma unroll
            for (int p = 0; p < 2; p++) {
                uint32_t t[4];
                ldsm_x4(t, baseB[p] + kB);
                bf[2 * p][0] = t[0]; bf[2 * p][1] = t[1];
                bf[2 * p + 1][0] = t[2]; bf[2 * p + 1][1] = t[3];
            }
            if (AFF == 1) {
                int kg = kb * 16 + ks * 8 + qt;
                float s_lo = scl[kg], h_lo = shf[kg];
                float s_hi = scl[kg + 4], h_hi = shf[kg + 4];
                #pragma unroll
                for (int mt = 0; mt < 4; mt++) {
                    af[mt][0] = __float_as_uint(s_lo * __uint_as_float(af[mt][0]) + h_lo);
                    af[mt][1] = __float_as_uint(s_lo * __uint_as_float(af[mt][1]) + h_lo);
                    af[mt][2] = __float_as_uint(s_hi * __uint_as_float(af[mt][2]) + h_hi);
                    af[mt][3] = __float_as_uint(s_hi * __uint_as_float(af[mt][3]) + h_hi);
                }
            }
            #pragma unroll
            for (int mt = 0; mt < 4; mt++)
                #pragma unroll
                for (int nt = 0; nt < 4; nt++)
                    mma_tf32(acc[mt][nt], af[mt], bf[nt]);
        }
        if (++st == 3) st = 0;
    }

    // epilogue (+ optional column-stats partials)
    float cs[8], cq[8];
    if (STATS) {
        #pragma unroll
        for (int j = 0; j < 8; j++) { cs[j] = 0.f; cq[j] = 0.f; }
    }

    #pragma unroll
    for (int mt = 0; mt < 4; mt++) {
        #pragma unroll
        for (int nt = 0; nt < 4; nt++) {
            int c  = col0 + wn + nt * 8 + 2 * qt;
            int r0 = row0 + wm + mt * 16 + qg;
            float b0 = bias[c], b1 = bias[c + 1];
            float s0 = 1.f, s1 = 1.f, h0 = 0.f, h1 = 0.f;
            if (AFF == 2) {
                s0 = scl[c]; s1 = scl[c + 1];
                h0 = shf[c]; h1 = shf[c + 1];
            }
            #pragma unroll
            for (int half = 0; half < 2; half++) {
                int r = r0 + half * 8;
                float vx = acc[mt][nt][half * 2 + 0] + b0;
                float vy = acc[mt][nt][half * 2 + 1] + b1;
                if (EPI == 1) {
                    vx = 0.5f * vx * (1.0f + erff(vx * 0.70710678118654752f));
                    vy = 0.5f * vy * (1.0f + erff(vy * 0.70710678118654752f));
                }
                size_t off = (size_t)r * Dout + c;
                if (EPI == 2) {
                    float2 rv = *(const float2*)(res + off);
                    if (AFF == 2) { vx += s0 * rv.x + h0; vy += s1 * rv.y + h1; }
                    else          { vx += rv.x;           vy += rv.y; }
                }
                if (STATS) {
                    cs[nt * 2 + 0] += vx; cq[nt * 2 + 0] += vx * vx;
                    cs[nt * 2 + 1] += vy; cq[nt * 2 + 1] += vy * vy;
                }
                *(float2*)(C + off) = make_float2(vx, vy);
            }
        }
    }

    if (STATS) {
        // reduce across qg (lanes differing in bits 2..4)
        #pragma unroll
        for (int j = 0; j < 8; j++) {
            #pragma unroll
            for (int m = 4; m <= 16; m <<= 1) {
                cs[j] += __shfl_xor_sync(0xffffffffu, cs[j], m);
                cq[j] += __shfl_xor_sync(0xffffffffu, cq[j], m);
            }
        }
        __syncthreads();                 // all MMA smem reads done; reuse smf
        float* ssum = smf;               // [2][128]
        float* ssq  = smf + 256;         // [2][128]
        int wrow = wid >> 2;
        if (lane < 4) {
            #pragma unroll
            for (int nt = 0; nt < 4; nt++) {
                #pragma unroll
                for (int p = 0; p < 2; p++) {
                    int cl = wn + nt * 8 + 2 * qt + p;
                    ssum[wrow * 128 + cl] = cs[nt * 2 + p];
                    ssq [wrow * 128 + cl] = cq[nt * 2 + p];
                }
            }
        }
        __syncthreads();
        if (tid < 128) {
            int slot = blockIdx.y * 512 + col0 + tid;
            g_psum[slot] = ssum[tid] + ssum[128 + tid];
            g_psq [slot] = ssq [tid] + ssq [128 + tid];
        }
    }
}

// ---------------------------------------------------------------------------
// Token embedding: circular Conv1d(P->D,k=3) + sinusoidal PE
// ---------------------------------------------------------------------------
#define EMB_SMEM_FLOATS (512 * 49 + 336)
__global__ void embed_kernel(const float* __restrict__ x_enc,
                             const float* __restrict__ tok_w,
                             float* __restrict__ h)
{
    extern __shared__ float sm[];
    float* w_sm = sm;
    float* x_sm = sm + 512 * 49;
    int bm = blockIdx.x;
    int b = bm >> 6, m = bm & 63;
    int tid = threadIdx.x;

    for (int i = tid; i < 512 * 48; i += 256) {
        int d = i / 48, u = i - d * 48;
        w_sm[d * 49 + u] = tok_w[i];
    }
    for (int l = tid; l < 336; l += 256)
        x_sm[l] = x_enc[(b * 336 + l) * 64 + m];
    __syncthreads();

    const float CLOG = -9.210340371976184f / 256.0f;
    int d0 = tid, d1 = tid + 256;
    float fr0 = expf((float)(d0 >> 1) * CLOG);
    float fr1 = expf((float)(d1 >> 1) * CLOG);

    for (int n = 0; n < NTOK; n++) {
        float a0 = 0.f, a1 = 0.f;
        #pragma unroll
        for (int t = 0; t < 3; t++) {
            int pp = n - 1 + t;
            pp = (pp < 0) ? (NTOK - 1) : (pp >= NTOK ? 0 : pp);
            const float* xp = x_sm + pp * 4;
            #pragma unroll
            for (int p = 0; p < 16; p++) {
                float xv = xp[p];
                a0 += xv * w_sm[d0 * 49 + p * 3 + t];
                a1 += xv * w_sm[d1 * 49 + p * 3 + t];
            }
        }
        float ang0 = (float)n * fr0, ang1 = (float)n * fr1;
        float pe0 = (d0 & 1) ? cosf(ang0) : sinf(ang0);
        float pe1 = (d1 & 1) ? cosf(ang1) : sinf(ang1);
        size_t base = ((size_t)bm * NTOK + n) * DM;
        h[base + d0] = a0 + pe0;
        h[base + d1] = a1 + pe1;
    }
}

// ---------------------------------------------------------------------------
// Fused attention per (bm, head): microtiled scores/AV + warp-parallel softmax
// ---------------------------------------------------------------------------
#define QPAD 17
#define SPAD 84
#define ATTN_SMEM_FLOATS (3 * 81 * 68 + 81 * SPAD)
__global__ void attn_kernel(const float* __restrict__ q,
                            const float* __restrict__ k,
                            const float* __restrict__ v,
                            float* __restrict__ o)
{
    extern __shared__ float sm[];
    float4* qs4 = (float4*)sm;
    float4* ks4 = qs4 + 81 * QPAD;
    float4* vs4 = ks4 + 81 * QPAD;
    float*  ss  = sm + 3 * 81 * 68;
    int bmh = blockIdx.x;
    int bm = bmh >> 3, hh = bmh & 7;
    int tid = threadIdx.x;
    int wid = tid >> 5, lane = tid & 31;
    size_t base = (size_t)bm * NTOK * DM + hh * EH;

    const float4* gq = (const float4*)(q + base);
    const float4* gk = (const float4*)(k + base);
    const float4* gv = (const float4*)(v + base);
    for (int i = tid; i < NTOK * 16; i += 256) {
        int n = i >> 4, e4 = i & 15;
        int gi = n * 128 + e4;
        qs4[n * QPAD + e4] = gq[gi];
        ks4[n * QPAD + e4] = gk[gi];
        vs4[n * QPAD + e4] = gv[gi];
    }
    __syncthreads();

    for (int i = tid; i < 729; i += 256) {
        int l0 = (i / 27) * 3, s0 = (i % 27) * 3;
        float acc[3][3] = {};
        #pragma unroll 4
        for (int e4 = 0; e4 < 16; e4++) {
            float4 qv[3], kv[3];
            #pragma unroll
            for (int j = 0; j < 3; j++) {
                qv[j] = qs4[(l0 + j) * QPAD + e4];
                kv[j] = ks4[(s0 + j) * QPAD + e4];
            }
            #pragma unroll
            for (int a = 0; a < 3; a++)
                #pragma unroll
                for (int b2 = 0; b2 < 3; b2++)
                    acc[a][b2] += qv[a].x * kv[b2].x + qv[a].y * kv[b2].y
                                + qv[a].z * kv[b2].z + qv[a].w * kv[b2].w;
        }
        #pragma unroll
        for (int a = 0; a < 3; a++)
            #pragma unroll
            for (int b2 = 0; b2 < 3; b2++)
                ss[(l0 + a) * SPAD + s0 + b2] = acc[a][b2] * 0.125f;
    }
    __syncthreads();

    // softmax: one warp per row, shfl reductions
    for (int l = wid; l < NTOK; l += 8) {
        float* row = ss + l * SPAD;
        float mx = -1e30f;
        for (int s2 = lane; s2 < NTOK; s2 += 32) mx = fmaxf(mx, row[s2]);
        #pragma unroll
        for (int m = 16; m; m >>= 1) mx = fmaxf(mx, __shfl_xor_sync(0xffffffffu, mx, m));
        float sum = 0.f;
        for (int s2 = lane; s2 < NTOK; s2 += 32) {
            float t = expf(row[s2] - mx);
            row[s2] = t; sum += t;
        }
        #pragma unroll
        for (int m = 16; m; m >>= 1) sum += __shfl_xor_sync(0xffffffffu, sum, m);
        float inv = 1.0f / sum;
        for (int s2 = lane; s2 < NTOK; s2 += 32) row[s2] *= inv;
    }
    __syncthreads();

    float4* go = (float4*)(o + base);
    for (int i = tid; i < 432; i += 256) {
        int l0 = (i / 16) * 3, e4 = i % 16;
        float4 acc[3] = {};
        for (int s2 = 0; s2 < NTOK; s2++) {
            float4 vv = vs4[s2 * QPAD + e4];
            #pragma unroll
            for (int j = 0; j < 3; j++) {
                float a = ss[(l0 + j) * SPAD + s2];
                acc[j].x += a * vv.x; acc[j].y += a * vv.y;
                acc[j].z += a * vv.z; acc[j].w += a * vv.w;
            }
        }
        #pragma unroll
        for (int j = 0; j < 3; j++)
            go[(l0 + j) * 128 + e4] = acc[j];
    }
}

// ---------------------------------------------------------------------------
// BN finalize: one block per channel, sum RTILES partials -> scale/shift
// ---------------------------------------------------------------------------
__global__ void bn_reduce2_kernel(const float* __restrict__ gamma,
                                  const float* __restrict__ beta,
                                  float* __restrict__ scl,
                                  float* __restrict__ shf)
{
    int c = blockIdx.x;
    int tid = threadIdx.x, wid = tid >> 5, lane = tid & 31;
    float s = 0.f, q = 0.f;
    for (int j = tid; j < RTILES; j += 256) {
        s += g_psum[j * 512 + c];
        q += g_psq [j * 512 + c];
    }
    #pragma unroll
    for (int m = 16; m; m >>= 1) {
        s += __shfl_xor_sync(0xffffffffu, s, m);
        q += __shfl_xor_sync(0xffffffffu, q, m);
    }
    __shared__ float rs[8], rq[8];
    if (lane == 0) { rs[wid] = s; rq[wid] = q; }
    __syncthreads();
    if (tid == 0) {
        float S = 0.f, Q = 0.f;
        #pragma unroll
        for (int w = 0; w < 8; w++) { S += rs[w]; Q += rq[w]; }
        const float invn = 1.0f / (float)RT;
        float mu  = S * invn;
        float var = Q * invn - mu * mu;
        float rinv = rsqrtf(var + 1e-5f);
        float sc = rinv * gamma[c];
        scl[c] = sc;
        shf[c] = beta[c] - mu * sc;
    }
}

__global__ void bn_norm_kernel(const float* __restrict__ y,
                               const float* __restrict__ scl,
                               const float* __restrict__ shf,
                               float* __restrict__ out)
{
    const int total = RT * DM / 4;
    for (int i = blockIdx.x * blockDim.x + threadIdx.x; i < total;
         i += gridDim.x * blockDim.x) {
        float4 vv = ((const float4*)y)[i];
        int c = (i & 127) * 4;
        float4 oo;
        oo.x = vv.x * scl[c + 0] + shf[c + 0];
        oo.y = vv.y * scl[c + 1] + shf[c + 1];
        oo.z = vv.z * scl[c + 2] + shf[c + 2];
        oo.w = vv.w * scl[c + 3] + shf[c + 3];
        ((float4*)out)[i] = oo;
    }
}

// ---------------------------------------------------------------------------
// Orchestration
// ---------------------------------------------------------------------------
extern "C" void kernel_launch(void* const* d_in, const int* in_sizes, int n_in,
                              void* d_out, int out_size)
{
    const float* x_enc = (const float*)d_in[0];
    const float* tok_w = (const float*)d_in[1];
    const float* wq  = (const float*)d_in[2];
    const float* bq  = (const float*)d_in[3];
    const float* wk  = (const float*)d_in[4];
    const float* bk  = (const float*)d_in[5];
    const float* wv  = (const float*)d_in[6];
    const float* bv  = (const float*)d_in[7];
    const float* wo  = (const float*)d_in[8];
    const float* bo  = (const float*)d_in[9];
    const float* c1w = (const float*)d_in[10];
    const float* c1b = (const float*)d_in[11];
    const float* c2w = (const float*)d_in[12];
    const float* c2b = (const float*)d_in[13];
    const float* g1  = (const float*)d_in[14];
    const float* be1 = (const float*)d_in[15];
    const float* g2  = (const float*)d_in[16];
    const float* be2 = (const float*)d_in[17];
    float* out = (float*)d_out;

    float *p_h, *p_q, *p_k, *p_v, *p_att, *p_y, *p_t, *p_scl, *p_shf;
    cudaGetSymbolAddress((void**)&p_h,   g_h);
    cudaGetSymbolAddress((void**)&p_q,   g_q);
    cudaGetSymbolAddress((void**)&p_k,   g_k);
    cudaGetSymbolAddress((void**)&p_v,   g_v);
    cudaGetSymbolAddress((void**)&p_att, g_att);
    cudaGetSymbolAddress((void**)&p_y,   g_y);
    cudaGetSymbolAddress((void**)&p_t,   g_t);
    cudaGetSymbolAddress((void**)&p_scl, g_bnscale);
    cudaGetSymbolAddress((void**)&p_shf, g_bnshift);
    float* scl0 = p_scl;       float* shf0 = p_shf;
    float* scl1 = p_scl + 512; float* shf1 = p_shf + 512;

    const int EMB_SMEM  = EMB_SMEM_FLOATS  * 4;
    const int ATTN_SMEM = ATTN_SMEM_FLOATS * 4;
    cudaFuncSetAttribute(embed_kernel,
        cudaFuncAttributeMaxDynamicSharedMemorySize, EMB_SMEM);
    cudaFuncSetAttribute(attn_kernel,
        cudaFuncAttributeMaxDynamicSharedMemorySize, ATTN_SMEM);
    cudaFuncSetAttribute(mma_gemm<0, 0, 0>,
        cudaFuncAttributeMaxDynamicSharedMemorySize, GEMM_SMEM);
    cudaFuncSetAttribute(mma_gemm<0, 1, 0>,
        cudaFuncAttributeMaxDynamicSharedMemorySize, GEMM_SMEM);
    cudaFuncSetAttribute(mma_gemm<2, 0, 1>,
        cudaFuncAttributeMaxDynamicSharedMemorySize, GEMM_SMEM);
    cudaFuncSetAttribute(mma_gemm<2, 2, 1>,
        cudaFuncAttributeMaxDynamicSharedMemorySize, GEMM_SMEM);
    cudaFuncSetAttribute(mma_gemm<1, 1, 0>,
        cudaFuncAttributeMaxDynamicSharedMemorySize, GEMM_SMEM);

    embed_kernel<<<2048, 256, EMB_SMEM>>>(x_enc, tok_w, p_h);

    for (int l = 0; l < NL; l++) {
        const int WOFF = l * DM * DM;
        const int FOFF = l * DFF * DM;

        if (l == 0) {
            mma_gemm<0, 0, 0><<<dim3(4, RTILES), 256, GEMM_SMEM>>>(p_h, wq + WOFF,
                bq + l * DM, nullptr, nullptr, nullptr, p_q, DM);
            mma_gemm<0, 0, 0><<<dim3(4, RTILES), 256, GEMM_SMEM>>>(p_h, wk + WOFF,
                bk + l * DM, nullptr, nullptr, nullptr, p_k, DM);
            mma_gemm<0, 0, 0><<<dim3(4, RTILES), 256, GEMM_SMEM>>>(p_h, wv + WOFF,
                bv + l * DM, nullptr, nullptr, nullptr, p_v, DM);
        } else {
            mma_gemm<0, 1, 0><<<dim3(4, RTILES), 256, GEMM_SMEM>>>(p_h, wq + WOFF,
                bq + l * DM, nullptr, scl1, shf1, p_q, DM);
            mma_gemm<0, 1, 0><<<dim3(4, RTILES), 256, GEMM_SMEM>>>(p_h, wk + WOFF,
                bk + l * DM, nullptr, scl1, shf1, p_k, DM);
            mma_gemm<0, 1, 0><<<dim3(4, RTILES), 256, GEMM_SMEM>>>(p_h, wv + WOFF,
                bv + l * DM, nullptr, scl1, shf1, p_v, DM);
        }

        attn_kernel<<<2048 * NH, 256, ATTN_SMEM>>>(p_q, p_k, p_v, p_att);

        if (l == 0)
            mma_gemm<2, 0, 1><<<dim3(4, RTILES), 256, GEMM_SMEM>>>(p_att, wo + WOFF,
                bo + l * DM, p_h, nullptr, nullptr, p_y, DM);
        else
            mma_gemm<2, 2, 1><<<dim3(4, RTILES), 256, GEMM_SMEM>>>(p_att, wo + WOFF,
                bo + l * DM, p_h, scl1, shf1, p_y, DM);

        bn_reduce2_kernel<<<512, 256>>>(g1 + l * DM, be1 + l * DM, scl0, shf0);

        mma_gemm<1, 1, 0><<<dim3(8, RTILES), 256, GEMM_SMEM>>>(p_y, c1w + FOFF,
            c1b + l * DFF, nullptr, scl0, shf0, p_t, DM);
        mma_gemm<2, 2, 1><<<dim3(4, RTILES), 256, GEMM_SMEM>>>(p_t, c2w + FOFF,
            c2b + l * DM, p_y, scl0, shf0, p_h, DFF);

        bn_reduce2_kernel<<<512, 256>>>(g2 + l * DM, be2 + l * DM, scl1, shf1);
    }

    bn_norm_kernel<<<4096, 256>>>(p_h, scl1, shf1, out);
}

// round 8
// speedup vs baseline: 1.2877x; 1.0648x over previous
#include <cuda_runtime.h>
#include <math.h>
#include <stdint.h>

// ---------------------------------------------------------------------------
// Problem constants
// ---------------------------------------------------------------------------
#define NTOK   81
#define DM     512
#define NH     8
#define EH     64
#define DFF    1024
#define NL     3
#define RT     (2048 * 81)           // 165888 tokens
#define RTILES (RT / 128)            // 1296

// ---------------------------------------------------------------------------
// Scratch (device globals: no cudaMalloc allowed)
// ---------------------------------------------------------------------------
__device__ float g_h  [RT * DM];
__device__ float g_q  [RT * DM];
__device__ float g_k  [RT * DM];
__device__ float g_v  [RT * DM];
__device__ float g_att[RT * DM];
__device__ float g_y  [RT * DM];
__device__ float g_t  [RT * DFF];
__device__ float g_psum[RTILES * 512];
__device__ float g_psq [RTILES * 512];
__device__ float g_bnscale[2 * 512];
__device__ float g_bnshift[2 * 512];

// ---------------------------------------------------------------------------
// PTX helpers
// ---------------------------------------------------------------------------
__device__ __forceinline__ uint32_t smem_u32(const void* p) {
    uint32_t a;
    asm("{ .reg .u64 t; cvta.to.shared.u64 t, %1; cvt.u32.u64 %0, t; }"
        : "=r"(a) : "l"(p));
    return a;
}

__device__ __forceinline__ void cp16(uint32_t dst, const void* src) {
    asm volatile("cp.async.cg.shared.global [%0], [%1], 16;"
                 :: "r"(dst), "l"(src) : "memory");
}
#define CP_COMMIT() asm volatile("cp.async.commit_group;" ::: "memory")

__device__ __forceinline__ void mma_tf32(float* c, const uint32_t* a, const uint32_t* b) {
    asm volatile(
        "mma.sync.aligned.m16n8k8.row.col.f32.tf32.tf32.f32 "
        "{%0,%1,%2,%3}, {%4,%5,%6,%7}, {%8,%9}, {%0,%1,%2,%3};"
        : "+f"(c[0]), "+f"(c[1]), "+f"(c[2]), "+f"(c[3])
        : "r"(a[0]), "r"(a[1]), "r"(a[2]), "r"(a[3]), "r"(b[0]), "r"(b[1]));
}

__device__ __forceinline__ void ldsm_x4(uint32_t* r, uint32_t addr) {
    asm volatile("ldmatrix.sync.aligned.m8n8.x4.shared.b16 {%0,%1,%2,%3}, [%4];"
        : "=r"(r[0]), "=r"(r[1]), "=r"(r[2]), "=r"(r[3]) : "r"(addr));
}

// ---------------------------------------------------------------------------
// TF32 GEMM: C[r,o] = sum_k A[r,k]*W[o,k] (+bias)
// CTA tile 128x128, BK=32, 8 warps (2x4), warp tile 64x32, 2 CTAs/SM.
// 3-stage cp.async.cg pipeline (36KB/stage, 108KB/CTA), barrier every 32 K.
// EPI: 0=bias, 1=bias+gelu, 2=bias+residual
// AFF: 0=none, 1=affine on A in-fragment (per-K), 2=affine on residual (per-col)
// STATS: 1 -> write per-CTA column sum/sumsq partials to g_psum/g_psq
// ---------------------------------------------------------------------------
#define APAD 36
#define A_HALF 18432                     // 128*36*4
#define STAGE_B 36864                    // A half + B half
#define GEMM_SMEM (3 * STAGE_B)          // 110592 B

template <int EPI, int AFF, int STATS>
__global__ __launch_bounds__(256, 2)
void mma_gemm(const float* __restrict__ A, const float* __restrict__ W,
              const float* __restrict__ bias, const float* __restrict__ res,
              const float* __restrict__ scl, const float* __restrict__ shf,
              float* __restrict__ C, int K)
{
    extern __shared__ float smf[];
    uint32_t sA = smem_u32(smf);
    uint32_t sB = sA + A_HALF;

    int tid  = threadIdx.x;
    int wid  = tid >> 5, lane = tid & 31;
    int wm   = (wid >> 2) * 64;
    int wn   = (wid & 3) * 32;
    int row0 = blockIdx.y * 128, col0 = blockIdx.x * 128;
    int Dout = gridDim.x * 128;
    int qg   = lane >> 2, qt = lane & 3;
    int lg   = lane >> 3, lr = lane & 7;

    uint32_t baseA[4], baseB[2];
    #pragma unroll
    for (int mt = 0; mt < 4; mt++)
        baseA[mt] = sA + (((wm + mt * 16 + (lg & 1) * 8 + lr) * APAD) + (lg >> 1) * 4) * 4;
    #pragma unroll
    for (int p = 0; p < 2; p++)
        baseB[p]  = sB + (((wn + (2 * p + (lg >> 1)) * 8 + lr) * APAD) + (lg & 1) * 4) * 4;

    // copy mapping: rows tid>>3 (+32*i), float4-slot tid&7
    int rr = tid >> 3, cc4 = tid & 7;
    const float* gA = A + (size_t)(row0 + rr) * K + cc4 * 4;
    const float* gW = W + (size_t)(col0 + rr) * K + cc4 * 4;
    uint32_t dsl = (uint32_t)(rr * APAD + cc4 * 4) * 4;

    auto issue = [&](int st, int kb2) {
        uint32_t o = st * STAGE_B + dsl;
        const float* pa = gA + kb2 * 32;
        const float* pw = gW + kb2 * 32;
        #pragma unroll
        for (int i = 0; i < 4; i++) {
            cp16(sA + o + i * (32 * APAD * 4), pa + (size_t)i * 32 * K);
            cp16(sB + o + i * (32 * APAD * 4), pw + (size_t)i * 32 * K);
        }
        CP_COMMIT();
    };

    int NKB = K / 32;
    issue(0, 0);
    issue(1, 1);

    float acc[4][4][4];
    #pragma unroll
    for (int mt = 0; mt < 4; mt++)
        #pragma unroll
        for (int nt = 0; nt < 4; nt++)
            #pragma unroll
            for (int j = 0; j < 4; j++) acc[mt][nt][j] = 0.f;

    int st = 0, nst = 2;
    for (int kb = 0; kb < NKB; kb++) {
        if (kb + 1 < NKB)
            asm volatile("cp.async.wait_group 1;" ::: "memory");
        else
            asm volatile("cp.async.wait_group 0;" ::: "memory");
        __syncthreads();
        if (kb + 2 < NKB) {
            issue(nst, kb + 2);
            if (++nst == 3) nst = 0;
        }

        uint32_t stOff = st * STAGE_B;
        #pragma unroll
        for (int ks = 0; ks < 4; ks++) {
            uint32_t kB = stOff + ks * 32;
            uint32_t af[4][4], bf[4][2];
            #pragma unroll
            for (int mt = 0; mt < 4; mt++)
                ldsm_x4(af[mt], baseA[mt] + kB);
            #pragma unroll
            for (int p = 0; p < 2; p++) {
                uint32_t t[4];
                ldsm_x4(t, baseB[p] + kB);
                bf[2 * p][0] = t[0]; bf[2 * p][1] = t[1];
                bf[2 * p + 1][0] = t[2]; bf[2 * p + 1][1] = t[3];
            }
            if (AFF == 1) {
                int kg = kb * 32 + ks * 8 + qt;
                float s_lo = scl[kg], h_lo = shf[kg];
                float s_hi = scl[kg + 4], h_hi = shf[kg + 4];
                #pragma unroll
                for (int mt = 0; mt < 4; mt++) {
                    af[mt][0] = __float_as_uint(s_lo * __uint_as_float(af[mt][0]) + h_lo);
                    af[mt][1] = __float_as_uint(s_lo * __uint_as_float(af[mt][1]) + h_lo);
                    af[mt][2] = __float_as_uint(s_hi * __uint_as_float(af[mt][2]) + h_hi);
                    af[mt][3] = __float_as_uint(s_hi * __uint_as_float(af[mt][3]) + h_hi);
                }
            }
            #pragma unroll
            for (int mt = 0; mt < 4; mt++)
                #pragma unroll
                for (int nt = 0; nt < 4; nt++)
                    mma_tf32(acc[mt][nt], af[mt], bf[nt]);
        }
        if (++st == 3) st = 0;
    }

    // epilogue (+ optional column-stats partials)
    float cs[8], cq[8];
    if (STATS) {
        #pragma unroll
        for (int j = 0; j < 8; j++) { cs[j] = 0.f; cq[j] = 0.f; }
    }

    #pragma unroll
    for (int mt = 0; mt < 4; mt++) {
        #pragma unroll
        for (int nt = 0; nt < 4; nt++) {
            int c  = col0 + wn + nt * 8 + 2 * qt;
            int r0 = row0 + wm + mt * 16 + qg;
            float b0 = bias[c], b1 = bias[c + 1];
            float s0 = 1.f, s1 = 1.f, h0 = 0.f, h1 = 0.f;
            if (AFF == 2) {
                s0 = scl[c]; s1 = scl[c + 1];
                h0 = shf[c]; h1 = shf[c + 1];
            }
            #pragma unroll
            for (int half = 0; half < 2; half++) {
                int r = r0 + half * 8;
                float vx = acc[mt][nt][half * 2 + 0] + b0;
                float vy = acc[mt][nt][half * 2 + 1] + b1;
                if (EPI == 1) {
                    vx = 0.5f * vx * (1.0f + erff(vx * 0.70710678118654752f));
                    vy = 0.5f * vy * (1.0f + erff(vy * 0.70710678118654752f));
                }
                size_t off = (size_t)r * Dout + c;
                if (EPI == 2) {
                    float2 rv = *(const float2*)(res + off);
                    if (AFF == 2) { vx += s0 * rv.x + h0; vy += s1 * rv.y + h1; }
                    else          { vx += rv.x;           vy += rv.y; }
                }
                if (STATS) {
                    cs[nt * 2 + 0] += vx; cq[nt * 2 + 0] += vx * vx;
                    cs[nt * 2 + 1] += vy; cq[nt * 2 + 1] += vy * vy;
                }
                *(float2*)(C + off) = make_float2(vx, vy);
            }
        }
    }

    if (STATS) {
        #pragma unroll
        for (int j = 0; j < 8; j++) {
            #pragma unroll
            for (int m = 4; m <= 16; m <<= 1) {
                cs[j] += __shfl_xor_sync(0xffffffffu, cs[j], m);
                cq[j] += __shfl_xor_sync(0xffffffffu, cq[j], m);
            }
        }
        __syncthreads();
        float* ssum = smf;               // [2][128]
        float* ssq  = smf + 256;         // [2][128]
        int wrow = wid >> 2;
        if (lane < 4) {
            #pragma unroll
            for (int nt = 0; nt < 4; nt++) {
                #pragma unroll
                for (int p = 0; p < 2; p++) {
                    int cl = wn + nt * 8 + 2 * qt + p;
                    ssum[wrow * 128 + cl] = cs[nt * 2 + p];
                    ssq [wrow * 128 + cl] = cq[nt * 2 + p];
                }
            }
        }
        __syncthreads();
        if (tid < 128) {
            int slot = blockIdx.y * 512 + col0 + tid;
            g_psum[slot] = ssum[tid] + ssum[128 + tid];
            g_psq [slot] = ssq [tid] + ssq [128 + tid];
        }
    }
}

// ---------------------------------------------------------------------------
// Token embedding: circular Conv1d(P->D,k=3) + sinusoidal PE
// ---------------------------------------------------------------------------
#define EMB_SMEM_FLOATS (512 * 49 + 336)
__global__ void embed_kernel(const float* __restrict__ x_enc,
                             const float* __restrict__ tok_w,
                             float* __restrict__ h)
{
    extern __shared__ float sm[];
    float* w_sm = sm;
    float* x_sm = sm + 512 * 49;
    int bm = blockIdx.x;
    int b = bm >> 6, m = bm & 63;
    int tid = threadIdx.x;

    for (int i = tid; i < 512 * 48; i += 256) {
        int d = i / 48, u = i - d * 48;
        w_sm[d * 49 + u] = tok_w[i];
    }
    for (int l = tid; l < 336; l += 256)
        x_sm[l] = x_enc[(b * 336 + l) * 64 + m];
    __syncthreads();

    const float CLOG = -9.210340371976184f / 256.0f;
    int d0 = tid, d1 = tid + 256;
    float fr0 = expf((float)(d0 >> 1) * CLOG);
    float fr1 = expf((float)(d1 >> 1) * CLOG);

    for (int n = 0; n < NTOK; n++) {
        float a0 = 0.f, a1 = 0.f;
        #pragma unroll
        for (int t = 0; t < 3; t++) {
            int pp = n - 1 + t;
            pp = (pp < 0) ? (NTOK - 1) : (pp >= NTOK ? 0 : pp);
            const float* xp = x_sm + pp * 4;
            #pragma unroll
            for (int p = 0; p < 16; p++) {
                float xv = xp[p];
                a0 += xv * w_sm[d0 * 49 + p * 3 + t];
                a1 += xv * w_sm[d1 * 49 + p * 3 + t];
            }
        }
        float ang0 = (float)n * fr0, ang1 = (float)n * fr1;
        float pe0 = (d0 & 1) ? cosf(ang0) : sinf(ang0);
        float pe1 = (d1 & 1) ? cosf(ang1) : sinf(ang1);
        size_t base = ((size_t)bm * NTOK + n) * DM;
        h[base + d0] = a0 + pe0;
        h[base + d1] = a1 + pe1;
    }
}

// ---------------------------------------------------------------------------
// Fused attention per (bm, head): microtiled scores/AV + warp-parallel softmax
// ---------------------------------------------------------------------------
#define QPAD 17
#define SPAD 84
#define ATTN_SMEM_FLOATS (3 * 81 * 68 + 81 * SPAD)
__global__ void attn_kernel(const float* __restrict__ q,
                            const float* __restrict__ k,
                            const float* __restrict__ v,
                            float* __restrict__ o)
{
    extern __shared__ float sm[];
    float4* qs4 = (float4*)sm;
    float4* ks4 = qs4 + 81 * QPAD;
    float4* vs4 = ks4 + 81 * QPAD;
    float*  ss  = sm + 3 * 81 * 68;
    int bmh = blockIdx.x;
    int bm = bmh >> 3, hh = bmh & 7;
    int tid = threadIdx.x;
    int wid = tid >> 5, lane = tid & 31;
    size_t base = (size_t)bm * NTOK * DM + hh * EH;

    const float4* gq = (const float4*)(q + base);
    const float4* gk = (const float4*)(k + base);
    const float4* gv = (const float4*)(v + base);
    for (int i = tid; i < NTOK * 16; i += 256) {
        int n = i >> 4, e4 = i & 15;
        int gi = n * 128 + e4;
        qs4[n * QPAD + e4] = gq[gi];
        ks4[n * QPAD + e4] = gk[gi];
        vs4[n * QPAD + e4] = gv[gi];
    }
    __syncthreads();

    for (int i = tid; i < 729; i += 256) {
        int l0 = (i / 27) * 3, s0 = (i % 27) * 3;
        float acc[3][3] = {};
        #pragma unroll 4
        for (int e4 = 0; e4 < 16; e4++) {
            float4 qv[3], kv[3];
            #pragma unroll
            for (int j = 0; j < 3; j++) {
                qv[j] = qs4[(l0 + j) * QPAD + e4];
                kv[j] = ks4[(s0 + j) * QPAD + e4];
            }
            #pragma unroll
            for (int a = 0; a < 3; a++)
                #pragma unroll
                for (int b2 = 0; b2 < 3; b2++)
                    acc[a][b2] += qv[a].x * kv[b2].x + qv[a].y * kv[b2].y
                                + qv[a].z * kv[b2].z + qv[a].w * kv[b2].w;
        }
        #pragma unroll
        for (int a = 0; a < 3; a++)
            #pragma unroll
            for (int b2 = 0; b2 < 3; b2++)
                ss[(l0 + a) * SPAD + s0 + b2] = acc[a][b2] * 0.125f;
    }
    __syncthreads();

    // softmax: one warp per row, shfl reductions
    for (int l = wid; l < NTOK; l += 8) {
        float* row = ss + l * SPAD;
        float mx = -1e30f;
        for (int s2 = lane; s2 < NTOK; s2 += 32) mx = fmaxf(mx, row[s2]);
        #pragma unroll
        for (int m = 16; m; m >>= 1) mx = fmaxf(mx, __shfl_xor_sync(0xffffffffu, mx, m));
        float sum = 0.f;
        for (int s2 = lane; s2 < NTOK; s2 += 32) {
            float t = __expf(row[s2] - mx);
            row[s2] = t; sum += t;
        }
        #pragma unroll
        for (int m = 16; m; m >>= 1) sum += __shfl_xor_sync(0xffffffffu, sum, m);
        float inv = 1.0f / sum;
        for (int s2 = lane; s2 < NTOK; s2 += 32) row[s2] *= inv;
    }
    __syncthreads();

    float4* go = (float4*)(o + base);
    for (int i = tid; i < 432; i += 256) {
        int l0 = (i / 16) * 3, e4 = i % 16;
        float4 acc[3] = {};
        for (int s2 = 0; s2 < NTOK; s2++) {
            float4 vv = vs4[s2 * QPAD + e4];
            #pragma unroll
            for (int j = 0; j < 3; j++) {
                float a = ss[(l0 + j) * SPAD + s2];
                acc[j].x += a * vv.x; acc[j].y += a * vv.y;
                acc[j].z += a * vv.z; acc[j].w += a * vv.w;
            }
        }
        #pragma unroll
        for (int j = 0; j < 3; j++)
            go[(l0 + j) * 128 + e4] = acc[j];
    }
}

// ---------------------------------------------------------------------------
// BN finalize: one block per channel, sum RTILES partials -> scale/shift
// ---------------------------------------------------------------------------
__global__ void bn_reduce2_kernel(const float* __restrict__ gamma,
                                  const float* __restrict__ beta,
                                  float* __restrict__ scl,
                                  float* __restrict__ shf)
{
    int c = blockIdx.x;
    int tid = threadIdx.x, wid = tid >> 5, lane = tid & 31;
    float s = 0.f, q = 0.f;
    for (int j = tid; j < RTILES; j += 256) {
        s += g_psum[j * 512 + c];
        q += g_psq [j * 512 + c];
    }
    #pragma unroll
    for (int m = 16; m; m >>= 1) {
        s += __shfl_xor_sync(0xffffffffu, s, m);
        q += __shfl_xor_sync(0xffffffffu, q, m);
    }
    __shared__ float rs[8], rq[8];
    if (lane == 0) { rs[wid] = s; rq[wid] = q; }
    __syncthreads();
    if (tid == 0) {
        float S = 0.f, Q = 0.f;
        #pragma unroll
        for (int w = 0; w < 8; w++) { S += rs[w]; Q += rq[w]; }
        const float invn = 1.0f / (float)RT;
        float mu  = S * invn;
        float var = Q * invn - mu * mu;
        float rinv = rsqrtf(var + 1e-5f);
        float sc = rinv * gamma[c];
        scl[c] = sc;
        shf[c] = beta[c] - mu * sc;
    }
}

__global__ void bn_norm_kernel(const float* __restrict__ y,
                               const float* __restrict__ scl,
                               const float* __restrict__ shf,
                               float* __restrict__ out)
{
    const int total = RT * DM / 4;
    for (int i = blockIdx.x * blockDim.x + threadIdx.x; i < total;
         i += gridDim.x * blockDim.x) {
        float4 vv = ((const float4*)y)[i];
        int c = (i & 127) * 4;
        float4 oo;
        oo.x = vv.x * scl[c + 0] + shf[c + 0];
        oo.y = vv.y * scl[c + 1] + shf[c + 1];
        oo.z = vv.z * scl[c + 2] + shf[c + 2];
        oo.w = vv.w * scl[c + 3] + shf[c + 3];
        ((float4*)out)[i] = oo;
    }
}

// ---------------------------------------------------------------------------
// Orchestration
// ---------------------------------------------------------------------------
extern "C" void kernel_launch(void* const* d_in, const int* in_sizes, int n_in,
                              void* d_out, int out_size)
{
    const float* x_enc = (const float*)d_in[0];
    const float* tok_w = (const float*)d_in[1];
    const float* wq  = (const float*)d_in[2];
    const float* bq  = (const float*)d_in[3];
    const float* wk  = (const float*)d_in[4];
    const float* bk  = (const float*)d_in[5];
    const float* wv  = (const float*)d_in[6];
    const float* bv  = (const float*)d_in[7];
    const float* wo  = (const float*)d_in[8];
    const float* bo  = (const float*)d_in[9];
    const float* c1w = (const float*)d_in[10];
    const float* c1b = (const float*)d_in[11];
    const float* c2w = (const float*)d_in[12];
    const float* c2b = (const float*)d_in[13];
    const float* g1  = (const float*)d_in[14];
    const float* be1 = (const float*)d_in[15];
    const float* g2  = (const float*)d_in[16];
    const float* be2 = (const float*)d_in[17];
    float* out = (float*)d_out;

    float *p_h, *p_q, *p_k, *p_v, *p_att, *p_y, *p_t, *p_scl, *p_shf;
    cudaGetSymbolAddress((void**)&p_h,   g_h);
    cudaGetSymbolAddress((void**)&p_q,   g_q);
    cudaGetSymbolAddress((void**)&p_k,   g_k);
    cudaGetSymbolAddress((void**)&p_v,   g_v);
    cudaGetSymbolAddress((void**)&p_att, g_att);
    cudaGetSymbolAddress((void**)&p_y,   g_y);
    cudaGetSymbolAddress((void**)&p_t,   g_t);
    cudaGetSymbolAddress((void**)&p_scl, g_bnscale);
    cudaGetSymbolAddress((void**)&p_shf, g_bnshift);
    float* scl0 = p_scl;       float* shf0 = p_shf;
    float* scl1 = p_scl + 512; float* shf1 = p_shf + 512;

    const int EMB_SMEM  = EMB_SMEM_FLOATS  * 4;
    const int ATTN_SMEM = ATTN_SMEM_FLOATS * 4;
    cudaFuncSetAttribute(embed_kernel,
        cudaFuncAttributeMaxDynamicSharedMemorySize, EMB_SMEM);
    cudaFuncSetAttribute(attn_kernel,
        cudaFuncAttributeMaxDynamicSharedMemorySize, ATTN_SMEM);
    cudaFuncSetAttribute(mma_gemm<0, 0, 0>,
        cudaFuncAttributeMaxDynamicSharedMemorySize, GEMM_SMEM);
    cudaFuncSetAttribute(mma_gemm<0, 1, 0>,
        cudaFuncAttributeMaxDynamicSharedMemorySize, GEMM_SMEM);
    cudaFuncSetAttribute(mma_gemm<2, 0, 1>,
        cudaFuncAttributeMaxDynamicSharedMemorySize, GEMM_SMEM);
    cudaFuncSetAttribute(mma_gemm<2, 2, 1>,
        cudaFuncAttributeMaxDynamicSharedMemorySize, GEMM_SMEM);
    cudaFuncSetAttribute(mma_gemm<1, 1, 0>,
        cudaFuncAttributeMaxDynamicSharedMemorySize, GEMM_SMEM);

    embed_kernel<<<2048, 256, EMB_SMEM>>>(x_enc, tok_w, p_h);

    for (int l = 0; l < NL; l++) {
        const int WOFF = l * DM * DM;
        const int FOFF = l * DFF * DM;

        if (l == 0) {
            mma_gemm<0, 0, 0><<<dim3(4, RTILES), 256, GEMM_SMEM>>>(p_h, wq + WOFF,
                bq + l * DM, nullptr, nullptr, nullptr, p_q, DM);
            mma_gemm<0, 0, 0><<<dim3(4, RTILES), 256, GEMM_SMEM>>>(p_h, wk + WOFF,
                bk + l * DM, nullptr, nullptr, nullptr, p_k, DM);
            mma_gemm<0, 0, 0><<<dim3(4, RTILES), 256, GEMM_SMEM>>>(p_h, wv + WOFF,
                bv + l * DM, nullptr, nullptr, nullptr, p_v, DM);
        } else {
            mma_gemm<0, 1, 0><<<dim3(4, RTILES), 256, GEMM_SMEM>>>(p_h, wq + WOFF,
                bq + l * DM, nullptr, scl1, shf1, p_q, DM);
            mma_gemm<0, 1, 0><<<dim3(4, RTILES), 256, GEMM_SMEM>>>(p_h, wk + WOFF,
                bk + l * DM, nullptr, scl1, shf1, p_k, DM);
            mma_gemm<0, 1, 0><<<dim3(4, RTILES), 256, GEMM_SMEM>>>(p_h, wv + WOFF,
                bv + l * DM, nullptr, scl1, shf1, p_v, DM);
        }

        attn_kernel<<<2048 * NH, 256, ATTN_SMEM>>>(p_q, p_k, p_v, p_att);

        if (l == 0)
            mma_gemm<2, 0, 1><<<dim3(4, RTILES), 256, GEMM_SMEM>>>(p_att, wo + WOFF,
                bo + l * DM, p_h, nullptr, nullptr, p_y, DM);
        else
            mma_gemm<2, 2, 1><<<dim3(4, RTILES), 256, GEMM_SMEM>>>(p_att, wo + WOFF,
                bo + l * DM, p_h, scl1, shf1, p_y, DM);

        bn_reduce2_kernel<<<512, 256>>>(g1 + l * DM, be1 + l * DM, scl0, shf0);

        mma_gemm<1, 1, 0><<<dim3(8, RTILES), 256, GEMM_SMEM>>>(p_y, c1w + FOFF,
            c1b + l * DFF, nullptr, scl0, shf0, p_t, DM);
        mma_gemm<2, 2, 1><<<dim3(4, RTILES), 256, GEMM_SMEM>>>(p_t, c2w + FOFF,
            c2b + l * DM, p_y, scl0, shf0, p_h, DFF);

        bn_reduce2_kernel<<<512, 256>>>(g2 + l * DM, be2 + l * DM, scl1, shf1);
    }

    bn_norm_kernel<<<4096, 256>>>(p_h, scl1, shf1, out);
}